// round 4
// baseline (speedup 1.0000x reference)
#include <cuda_runtime.h>
#include <cstdint>

// Problem constants (fixed-shape problem: B=8, S=8192, D=256, K=2048)
#define N_PTS   65536
#define D_DIM   256
#define K_CODES 2048

#define DECAY_F 0.99f
#define OMD_F   0.01f     // 1 - DECAY
#define EPS_F   1e-6f

// Output layout (float32, concatenated in reference return order)
#define OFF_Q   0
#define OFF_IND (N_PTS * D_DIM)                    // 16777216
#define OFF_CS  (OFF_IND + N_PTS)                  // 16842752
#define OFF_AVG (OFF_CS + K_CODES)                 // 16844800
#define OFF_EMB (OFF_AVG + K_CODES * D_DIM)        // 17369088

// ---------------------------------------------------------------------------
// Device scratch (no allocations allowed)
// ---------------------------------------------------------------------------
__device__ int   g_idx[N_PTS];
__device__ float g_counts[K_CODES];
__device__ float g_esum[K_CODES * D_DIM];
__device__ float g_ehn[K_CODES];     // 0.5 * ||e_k||^2
__device__ float g_total;

// ---------------------------------------------------------------------------
// Packed f32x2 helpers (B300: FFMA 3-reg is half rate; f32x2 is the fast path)
// ---------------------------------------------------------------------------
__device__ __forceinline__ unsigned long long fma2(unsigned long long a,
                                                   unsigned long long b,
                                                   unsigned long long c) {
    unsigned long long d;
    asm("fma.rn.f32x2 %0, %1, %2, %3;" : "=l"(d) : "l"(a), "l"(b), "l"(c));
    return d;
}
__device__ __forceinline__ unsigned long long dup2(float v) {
    unsigned long long d;
    unsigned int u = __float_as_uint(v);
    asm("mov.b64 %0, {%1, %1};" : "=l"(d) : "r"(u));
    return d;
}
__device__ __forceinline__ void unpack2(unsigned long long p, float& lo, float& hi) {
    asm("mov.b64 {%0, %1}, %2;" : "=f"(lo), "=f"(hi) : "l"(p));
}

// ---------------------------------------------------------------------------
// Zero the scratch accumulators (graph replays must be deterministic)
// ---------------------------------------------------------------------------
__global__ void zero_kernel() {
    int i = blockIdx.x * blockDim.x + threadIdx.x;
    if (i < K_CODES * D_DIM) g_esum[i] = 0.0f;
    if (i < K_CODES)         g_counts[i] = 0.0f;
    if (i == 0)              g_total = 0.0f;
}

// ---------------------------------------------------------------------------
// Precompute 0.5*||e_k||^2  (2048 blocks x 64 threads, float4 per thread)
// ---------------------------------------------------------------------------
__global__ void ehn_kernel(const float* __restrict__ embed) {
    const int k = blockIdx.x;
    const int t = threadIdx.x;  // 0..63
    float4 v = *(const float4*)(embed + (size_t)k * D_DIM + t * 4);
    float s = v.x * v.x + v.y * v.y + v.z * v.z + v.w * v.w;
#pragma unroll
    for (int o = 16; o > 0; o >>= 1) s += __shfl_xor_sync(0xffffffffu, s, o);
    __shared__ float sh[2];
    if ((t & 31) == 0) sh[t >> 5] = s;
    __syncthreads();
    if (t == 0) g_ehn[k] = 0.5f * (sh[0] + sh[1]);
}

// ---------------------------------------------------------------------------
// Fused distance GEMM + argmax(x.e - ||e||^2/2)  ==  argmin distance
// Block tile 128x128, thread tile 8x8, f32x2 packed accumulators,
// double-buffered smem. Grid = N/128 = 512 blocks, 256 threads.
// ---------------------------------------------------------------------------
#define BM  128
#define BN  128
#define DK  16
#define LDA 132   // BM + 4 pad: keeps 16B alignment, 2-way STS conflicts max

__global__ __launch_bounds__(256, 1)
void argmin_kernel(const float* __restrict__ x, const float* __restrict__ embed) {
    __shared__ float Xs[2][DK][LDA];
    __shared__ float Es[2][DK][LDA];

    const int tid  = threadIdx.x;
    const int tx   = tid & 15;   // col group
    const int ty   = tid >> 4;   // row group
    const int row0 = blockIdx.x * BM;
    const int lrow = tid >> 2;        // 0..63 (loader row)
    const int ld4  = (tid & 3) * 4;   // 0,4,8,12 (loader d offset)

    float bestv[8];
    int   besti[8];
#pragma unroll
    for (int i = 0; i < 8; i++) { bestv[i] = -3.4e38f; besti[i] = 0; }

    const float* xb0 = x + (size_t)(row0 + lrow) * D_DIM + ld4;
    const float* xb1 = x + (size_t)(row0 + lrow + 64) * D_DIM + ld4;

    for (int kt = 0; kt < K_CODES / BN; kt++) {
        const int col0 = kt * BN;
        const float* eb0 = embed + (size_t)(col0 + lrow) * D_DIM + ld4;
        const float* eb1 = embed + (size_t)(col0 + lrow + 64) * D_DIM + ld4;

        unsigned long long acc[8][4];
#pragma unroll
        for (int i = 0; i < 8; i++)
#pragma unroll
            for (int j = 0; j < 4; j++) acc[i][j] = 0ULL;

        // prologue: chunk 0 -> smem buffer 0 (transposed: [d][row])
        {
            float4 xa = *(const float4*)(xb0);
            float4 xc = *(const float4*)(xb1);
            float4 ea = *(const float4*)(eb0);
            float4 ec = *(const float4*)(eb1);
            Xs[0][ld4 + 0][lrow] = xa.x; Xs[0][ld4 + 1][lrow] = xa.y;
            Xs[0][ld4 + 2][lrow] = xa.z; Xs[0][ld4 + 3][lrow] = xa.w;
            Xs[0][ld4 + 0][lrow + 64] = xc.x; Xs[0][ld4 + 1][lrow + 64] = xc.y;
            Xs[0][ld4 + 2][lrow + 64] = xc.z; Xs[0][ld4 + 3][lrow + 64] = xc.w;
            Es[0][ld4 + 0][lrow] = ea.x; Es[0][ld4 + 1][lrow] = ea.y;
            Es[0][ld4 + 2][lrow] = ea.z; Es[0][ld4 + 3][lrow] = ea.w;
            Es[0][ld4 + 0][lrow + 64] = ec.x; Es[0][ld4 + 1][lrow + 64] = ec.y;
            Es[0][ld4 + 2][lrow + 64] = ec.z; Es[0][ld4 + 3][lrow + 64] = ec.w;
        }
        __syncthreads();

        int buf = 0;
        for (int c = 0; c < D_DIM / DK; ++c) {
            const int dn = (c + 1) * DK;
            float4 nxa, nxc, nea, nec;
            const bool more = (dn < D_DIM);
            if (more) {
                nxa = *(const float4*)(xb0 + dn);
                nxc = *(const float4*)(xb1 + dn);
                nea = *(const float4*)(eb0 + dn);
                nec = *(const float4*)(eb1 + dn);
            }
            // compute on current buffer
#pragma unroll
            for (int d = 0; d < DK; d++) {
                float4 a0 = *(const float4*)&Xs[buf][d][ty * 8];
                float4 a1 = *(const float4*)&Xs[buf][d][ty * 8 + 4];
                const ulonglong2* bp = (const ulonglong2*)&Es[buf][d][tx * 8];
                ulonglong2 b0 = bp[0];
                ulonglong2 b1 = bp[1];
                unsigned long long a2[8];
                a2[0] = dup2(a0.x); a2[1] = dup2(a0.y);
                a2[2] = dup2(a0.z); a2[3] = dup2(a0.w);
                a2[4] = dup2(a1.x); a2[5] = dup2(a1.y);
                a2[6] = dup2(a1.z); a2[7] = dup2(a1.w);
#pragma unroll
                for (int i = 0; i < 8; i++) {
                    acc[i][0] = fma2(a2[i], b0.x, acc[i][0]);
                    acc[i][1] = fma2(a2[i], b0.y, acc[i][1]);
                    acc[i][2] = fma2(a2[i], b1.x, acc[i][2]);
                    acc[i][3] = fma2(a2[i], b1.y, acc[i][3]);
                }
            }
            if (more) {
                const int nb = buf ^ 1;
                Xs[nb][ld4 + 0][lrow] = nxa.x; Xs[nb][ld4 + 1][lrow] = nxa.y;
                Xs[nb][ld4 + 2][lrow] = nxa.z; Xs[nb][ld4 + 3][lrow] = nxa.w;
                Xs[nb][ld4 + 0][lrow + 64] = nxc.x; Xs[nb][ld4 + 1][lrow + 64] = nxc.y;
                Xs[nb][ld4 + 2][lrow + 64] = nxc.z; Xs[nb][ld4 + 3][lrow + 64] = nxc.w;
                Es[nb][ld4 + 0][lrow] = nea.x; Es[nb][ld4 + 1][lrow] = nea.y;
                Es[nb][ld4 + 2][lrow] = nea.z; Es[nb][ld4 + 3][lrow] = nea.w;
                Es[nb][ld4 + 0][lrow + 64] = nec.x; Es[nb][ld4 + 1][lrow + 64] = nec.y;
                Es[nb][ld4 + 2][lrow + 64] = nec.z; Es[nb][ld4 + 3][lrow + 64] = nec.w;
            }
            __syncthreads();
            buf ^= 1;
        }

        // epilogue: running argmax with ascending-column order (tie -> lowest idx,
        // matching jnp.argmin's first-min semantics)
#pragma unroll
        for (int jp = 0; jp < 4; jp++) {
            const int cc = col0 + tx * 8 + jp * 2;
            const float h0 = g_ehn[cc];
            const float h1 = g_ehn[cc + 1];
#pragma unroll
            for (int i = 0; i < 8; i++) {
                float lo, hi;
                unpack2(acc[i][jp], lo, hi);
                const float s0 = lo - h0;
                const float s1 = hi - h1;
                if (s0 > bestv[i]) { bestv[i] = s0; besti[i] = cc; }
                if (s1 > bestv[i]) { bestv[i] = s1; besti[i] = cc + 1; }
            }
        }
    }

    // cross-thread (tx) reduction per row, reusing smem
    float* rv = (float*)Xs;   // 16*128 floats, fits in Xs
    int*   ri = (int*)Es;
#pragma unroll
    for (int i = 0; i < 8; i++) {
        rv[tx * BM + ty * 8 + i] = bestv[i];
        ri[tx * BM + ty * 8 + i] = besti[i];
    }
    __syncthreads();
    if (tid < BM) {
        float bv = rv[tid];
        int   bi = ri[tid];
        for (int t = 1; t < 16; t++) {   // ascending t == ascending cols
            const float v = rv[t * BM + tid];
            const int   ii = ri[t * BM + tid];
            if (v > bv || (v == bv && ii < bi)) { bv = v; bi = ii; }
        }
        g_idx[row0 + tid] = bi;
    }
}

// ---------------------------------------------------------------------------
// Gather quantize rows + scatter counts / embed_sum via L2 float atomics.
// Grid = N blocks x 64 threads (float4 lanes over D=256).
// ---------------------------------------------------------------------------
__global__ void gather_scatter_kernel(const float* __restrict__ x,
                                      const float* __restrict__ embed,
                                      float* __restrict__ out) {
    const int row = blockIdx.x;
    const int t   = threadIdx.x;   // 0..63
    const int k   = g_idx[row];
    const int dof = t * 4;

    float4 e = *(const float4*)(embed + (size_t)k * D_DIM + dof);
    *(float4*)(out + OFF_Q + (size_t)row * D_DIM + dof) = e;

    float4 xv = *(const float4*)(x + (size_t)row * D_DIM + dof);
    float* es = &g_esum[k * D_DIM + dof];
    atomicAdd(es + 0, xv.x);
    atomicAdd(es + 1, xv.y);
    atomicAdd(es + 2, xv.z);
    atomicAdd(es + 3, xv.w);

    if (t == 0) {
        out[OFF_IND + row] = (float)k;
        atomicAdd(&g_counts[k], 1.0f);
    }
}

// ---------------------------------------------------------------------------
// Finalize 1: new_cluster_size + total (single block)
// ---------------------------------------------------------------------------
__global__ void finalize1_kernel(const float* __restrict__ cluster_size,
                                 float* __restrict__ out) {
    const int t = threadIdx.x;  // 1024 threads
    float s = 0.0f;
    for (int i = t; i < K_CODES; i += 1024) {
        const float v = cluster_size[i] * DECAY_F + OMD_F * g_counts[i];
        out[OFF_CS + i] = v;
        s += v;
    }
#pragma unroll
    for (int o = 16; o > 0; o >>= 1) s += __shfl_xor_sync(0xffffffffu, s, o);
    __shared__ float sh[32];
    if ((t & 31) == 0) sh[t >> 5] = s;
    __syncthreads();
    if (t < 32) {
        float v = sh[t];
#pragma unroll
        for (int o = 16; o > 0; o >>= 1) v += __shfl_xor_sync(0xffffffffu, v, o);
        if (t == 0) g_total = v;
    }
}

// ---------------------------------------------------------------------------
// Finalize 2: new_embed_avg and new_embed (grid = K blocks x 64 threads)
// ---------------------------------------------------------------------------
__global__ void finalize2_kernel(const float* __restrict__ embed_avg,
                                 float* __restrict__ out) {
    const int k = blockIdx.x;
    const int t = threadIdx.x;  // 0..63
    const float ncs   = out[OFF_CS + k];
    const float total = g_total;
    const float smoothed = (ncs + EPS_F) / (total + EPS_F * (float)K_CODES) * total;

    const int base = k * D_DIM + t * 4;
    float4 ea = *(const float4*)(embed_avg + base);
    float4 es = *(const float4*)(&g_esum[base]);
    float4 nav;
    nav.x = ea.x * DECAY_F + OMD_F * es.x;
    nav.y = ea.y * DECAY_F + OMD_F * es.y;
    nav.z = ea.z * DECAY_F + OMD_F * es.z;
    nav.w = ea.w * DECAY_F + OMD_F * es.w;
    *(float4*)(out + OFF_AVG + base) = nav;

    float4 ne;
    ne.x = nav.x / smoothed;
    ne.y = nav.y / smoothed;
    ne.z = nav.z / smoothed;
    ne.w = nav.w / smoothed;
    *(float4*)(out + OFF_EMB + base) = ne;
}

// ---------------------------------------------------------------------------
// Launch
// ---------------------------------------------------------------------------
extern "C" void kernel_launch(void* const* d_in, const int* in_sizes, int n_in,
                              void* d_out, int out_size) {
    const float* x         = (const float*)d_in[0];  // [B,S,D] fp32
    const float* embed     = (const float*)d_in[1];  // [K,D]
    const float* csize     = (const float*)d_in[2];  // [K]
    const float* embed_avg = (const float*)d_in[3];  // [K,D]
    float* out = (float*)d_out;

    zero_kernel<<<(K_CODES * D_DIM + 255) / 256, 256>>>();
    ehn_kernel<<<K_CODES, 64>>>(embed);
    argmin_kernel<<<N_PTS / BM, 256>>>(x, embed);
    gather_scatter_kernel<<<N_PTS, 64>>>(x, embed, out);
    finalize1_kernel<<<1, 1024>>>(csize, out);
    finalize2_kernel<<<K_CODES, 64>>>(embed_avg, out);
}